// round 11
// baseline (speedup 1.0000x reference)
#include <cuda_runtime.h>
#include <cstdint>

// Zero-initialized at load; last-ticket block self-resets -> 1-node graph.
struct State { double acc; unsigned long long count; };
__device__ State g_state;

static constexpr int BLOCKS  = 592;    // 4 blocks/SM (needs <=64 regs), persistent
static constexpr int THREADS = 256;    // 8 warps/block
static constexpr int WARPS_TOTAL = BLOCKS * (THREADS / 32);

// Half-row ping-pong: live data = 2 x 4 float4 (32 regs) so 4 blocks/SM fit.
// Per row: issue half1 -> consume half0 -> issue next row's half0 -> consume
// half1 -> serial tail. More resident warps (8/SMSP) smooth LSU issue gaps.
__global__ __launch_bounds__(THREADS, 4)
void cosine_loss_kernel(const float* __restrict__ logits,
                        const int* __restrict__ labels,
                        int N, int C, float* __restrict__ out, double inv_n) {
    const int lane  = threadIdx.x & 31;
    const int warp_in_block = threadIdx.x >> 5;
    const int gwarp = blockIdx.x * (THREADS >> 5) + warp_in_block;
    const int W = WARPS_TOTAL;

    double local = 0.0;

    float4 a[4], b[4];
    int lab = 0;
    int row = gwarp;

    // Prologue: half0 (chunks 0..3) of the first row + its label.
    if (row < N) {
        const float4* __restrict__ row4 =
            reinterpret_cast<const float4*>(logits + (size_t)row * (size_t)C);
        lab = __ldg(labels + row);
        #pragma unroll
        for (int k = 0; k < 4; k++)
            a[k] = __ldcs(row4 + lane + 32 * k);
    }

    while (row < N) {
        const float4* __restrict__ row4 =
            reinterpret_cast<const float4*>(logits + (size_t)row * (size_t)C);

        // Issue half1 of current row (chunks 4..6 + 26-wide tail).
        #pragma unroll
        for (int k = 0; k < 3; k++)
            b[k] = __ldcs(row4 + lane + 32 * (4 + k));
        b[3] = make_float4(0.f, 0.f, 0.f, 0.f);
        if (lane < 26)
            b[3] = __ldcs(row4 + lane + 224);

        const int labc = lab;
        const int j4   = labc >> 2;
        const int comp = labc & 3;
        const int lane_owner = j4 & 31;

        // Consume half0 (loads issued one half-step ago).
        float s0 = 0.f, s1 = 0.f, s2 = 0.f, s3 = 0.f;
        float dot_l = 0.0f;
        #pragma unroll
        for (int k = 0; k < 4; k++) {
            if (j4 == lane + 32 * k) {
                dot_l = (comp == 0) ? a[k].x :
                        (comp == 1) ? a[k].y :
                        (comp == 2) ? a[k].z : a[k].w;
            }
            s0 = fmaf(a[k].x, a[k].x, s0);
            s1 = fmaf(a[k].y, a[k].y, s1);
            s2 = fmaf(a[k].z, a[k].z, s2);
            s3 = fmaf(a[k].w, a[k].w, s3);
        }

        // Issue half0 of the NEXT row (a is dead).
        const int next = row + W;
        if (next < N) {
            const float4* __restrict__ nrow4 =
                reinterpret_cast<const float4*>(logits + (size_t)next * (size_t)C);
            lab = __ldg(labels + next);
            #pragma unroll
            for (int k = 0; k < 4; k++)
                a[k] = __ldcs(nrow4 + lane + 32 * k);
        }

        // Consume half1.
        #pragma unroll
        for (int k = 0; k < 3; k++) {
            if (j4 == lane + 32 * (4 + k)) {
                dot_l = (comp == 0) ? b[k].x :
                        (comp == 1) ? b[k].y :
                        (comp == 2) ? b[k].z : b[k].w;
            }
            s0 = fmaf(b[k].x, b[k].x, s0);
            s1 = fmaf(b[k].y, b[k].y, s1);
            s2 = fmaf(b[k].z, b[k].z, s2);
            s3 = fmaf(b[k].w, b[k].w, s3);
        }
        if (j4 == lane + 224) {
            dot_l = (comp == 0) ? b[3].x :
                    (comp == 1) ? b[3].y :
                    (comp == 2) ? b[3].z : b[3].w;
        }
        s0 = fmaf(b[3].x, b[3].x, s0);
        s1 = fmaf(b[3].y, b[3].y, s1);
        s2 = fmaf(b[3].z, b[3].z, s2);
        s3 = fmaf(b[3].w, b[3].w, s3);

        // Serial tail, behind the next row's in-flight half0 loads.
        float s = (s0 + s1) + (s2 + s3);
        #pragma unroll
        for (int o = 16; o > 0; o >>= 1)
            s += __shfl_xor_sync(0xFFFFFFFFu, s, o);
        const float dot = __shfl_sync(0xFFFFFFFFu, dot_l, lane_owner);

        if (lane == 0) {
            const float cosv = dot / fmaxf(sqrtf(s), 1e-8f);
            local += 1.0 - (double)cosv;
        }

        row = next;
    }

    // Block reduction, once per block.
    __shared__ double sh[THREADS >> 5];
    if (lane == 0) sh[warp_in_block] = local;
    __syncthreads();

    if (threadIdx.x == 0) {
        double t = 0.0;
        #pragma unroll
        for (int i = 0; i < (THREADS >> 5); i++) t += sh[i];
        atomicAdd(&g_state.acc, t);

        __threadfence();
        unsigned long long ticket = atomicAdd(&g_state.count, 1ULL);
        if (ticket == (unsigned long long)gridDim.x - 1ULL) {
            double acc = *(volatile double*)&g_state.acc;
            *out = (float)(acc * inv_n);
            g_state.acc = 0.0;
            __threadfence();
            g_state.count = 0ULL;
        }
    }
}

extern "C" void kernel_launch(void* const* d_in, const int* in_sizes, int n_in,
                              void* d_out, int out_size) {
    const float* logits = (const float*)d_in[0];
    const int*   labels = (const int*)d_in[1];
    float* out = (float*)d_out;

    const int N = in_sizes[1];          // rows == labels
    const int C = in_sizes[0] / N;      // 1000

    cosine_loss_kernel<<<BLOCKS, THREADS>>>(logits, labels, N, C, out,
                                            1.0 / (double)N);
}

// round 13
// speedup vs baseline: 1.0190x; 1.0190x over previous
#include <cuda_runtime.h>
#include <cstdint>

// Zero-initialized at module load; the last-ticket block resets it to zero at
// the end of every call, so no per-call memset node is needed (1-node graph).
struct State { double acc; unsigned long long count; };
__device__ State g_state;   // static init = {0, 0}

static constexpr int BLOCKS  = 444;    // 3 blocks/SM resident (80 regs), persistent
static constexpr int THREADS = 256;    // 8 warps/block
static constexpr int WARPS_TOTAL = BLOCKS * (THREADS / 32);

// Measured-best kernel (R10): software-pipelined persistent warps with a
// snapshot double-buffer; the label component is extracted in-pass from the
// streamed float4s (no separate gather load).
__global__ __launch_bounds__(THREADS)
void cosine_loss_kernel(const float* __restrict__ logits,
                        const int* __restrict__ labels,
                        int N, int C, float* __restrict__ out, double inv_n) {
    const int lane  = threadIdx.x & 31;
    const int warp_in_block = threadIdx.x >> 5;
    const int gwarp = blockIdx.x * (THREADS >> 5) + warp_in_block;

    double local = 0.0;

    int row = gwarp;
    float4 v[8];
    int lab = 0;

    // Prologue: loads for the first row.
    if (row < N) {
        const float4* __restrict__ row4 =
            reinterpret_cast<const float4*>(logits + (size_t)row * (size_t)C);
        lab = __ldg(labels + row);
        #pragma unroll
        for (int k = 0; k < 7; k++)
            v[k] = __ldcs(row4 + lane + 32 * k);
        v[7] = make_float4(0.f, 0.f, 0.f, 0.f);
        if (lane < 26)
            v[7] = __ldcs(row4 + lane + 224);
    }

    while (row < N) {
        // Snapshot current row, then issue next row's loads immediately.
        float4 cur[8];
        #pragma unroll
        for (int k = 0; k < 8; k++) cur[k] = v[k];
        const int labc = lab;

        const int next = row + WARPS_TOTAL;
        if (next < N) {
            const float4* __restrict__ row4 =
                reinterpret_cast<const float4*>(logits + (size_t)next * (size_t)C);
            lab = __ldg(labels + next);
            #pragma unroll
            for (int k = 0; k < 7; k++)
                v[k] = __ldcs(row4 + lane + 32 * k);
            v[7] = make_float4(0.f, 0.f, 0.f, 0.f);
            if (lane < 26)
                v[7] = __ldcs(row4 + lane + 224);
        }

        // Reduce current row; extract the label component in-pass.
        const int j4   = labc >> 2;          // float4 index within row [0,250)
        const int comp = labc & 3;
        const int lane_owner = j4 & 31;

        float s = 0.0f;
        float dot_l = 0.0f;
        #pragma unroll
        for (int k = 0; k < 8; k++) {
            if (j4 == lane + 32 * k) {
                dot_l = (comp == 0) ? cur[k].x :
                        (comp == 1) ? cur[k].y :
                        (comp == 2) ? cur[k].z : cur[k].w;
            }
            s = fmaf(cur[k].x, cur[k].x, s);
            s = fmaf(cur[k].y, cur[k].y, s);
            s = fmaf(cur[k].z, cur[k].z, s);
            s = fmaf(cur[k].w, cur[k].w, s);
        }
        #pragma unroll
        for (int o = 16; o > 0; o >>= 1)
            s += __shfl_xor_sync(0xFFFFFFFFu, s, o);
        const float dot = __shfl_sync(0xFFFFFFFFu, dot_l, lane_owner);

        if (lane == 0) {
            const float cosv = dot / fmaxf(sqrtf(s), 1e-8f);
            local += 1.0 - (double)cosv;
        }

        row = next;
    }

    // Block reduction, once per block.
    __shared__ double sh[THREADS >> 5];
    if (lane == 0) sh[warp_in_block] = local;
    __syncthreads();

    if (threadIdx.x == 0) {
        double t = 0.0;
        #pragma unroll
        for (int i = 0; i < (THREADS >> 5); i++) t += sh[i];
        atomicAdd(&g_state.acc, t);

        __threadfence();
        unsigned long long ticket = atomicAdd(&g_state.count, 1ULL);
        if (ticket == (unsigned long long)gridDim.x - 1ULL) {
            // All gridDim.x accumulations are complete (ticket order).
            double acc = *(volatile double*)&g_state.acc;
            *out = (float)(acc * inv_n);
            // Self-reset so the next call starts from a zeroed state:
            // no memset node needed -> 1-node graph.
            g_state.acc = 0.0;
            __threadfence();
            g_state.count = 0ULL;
        }
    }
}

extern "C" void kernel_launch(void* const* d_in, const int* in_sizes, int n_in,
                              void* d_out, int out_size) {
    const float* logits = (const float*)d_in[0];
    const int*   labels = (const int*)d_in[1];
    float* out = (float*)d_out;

    const int N = in_sizes[1];          // rows == labels
    const int C = in_sizes[0] / N;      // 1000

    cosine_loss_kernel<<<BLOCKS, THREADS>>>(logits, labels, N, C, out,
                                            1.0 / (double)N);
}